// round 1
// baseline (speedup 1.0000x reference)
#include <cuda_runtime.h>
#include <cstdint>
#include <cstddef>

#define DECAY 0.9f

#define B_ 2
#define S_ 2048
#define V_ 32000
#define E_ 1024
#define H_ 2048
#define M_ (B_*S_)   // 4096 rows

// Scratch (allocation-free rule: device globals)
__device__ float g_buf1[(size_t)M_ * H_];   // 32 MB: cur1 / spikes1 (in-place)
__device__ float g_buf2[(size_t)M_ * E_];   // 16 MB: cur2 / spikes2 (in-place)
__device__ int   g_ids_is64;

// ---------------------------------------------------------------------------
// helpers
// ---------------------------------------------------------------------------
__device__ __forceinline__ float tf32r(float x) {
    unsigned u; asm("cvt.rna.tf32.f32 %0, %1;" : "=r"(u) : "f"(x));
    return __uint_as_float(u);
}
__device__ __forceinline__ float fast_ex2(float x) {
    float y; asm("ex2.approx.f32 %0, %1;" : "=f"(y) : "f"(x)); return y;
}
__device__ __forceinline__ float fast_rcp(float x) {
    float y; asm("rcp.approx.f32 %0, %1;" : "=f"(y) : "f"(x)); return y;
}
__device__ __forceinline__ void mma8(float* c, const unsigned* a, const unsigned* b) {
    asm volatile(
        "mma.sync.aligned.m16n8k8.row.col.f32.tf32.tf32.f32 "
        "{%0,%1,%2,%3}, {%4,%5,%6,%7}, {%8,%9}, {%0,%1,%2,%3};\n"
        : "+f"(c[0]), "+f"(c[1]), "+f"(c[2]), "+f"(c[3])
        : "r"(a[0]), "r"(a[1]), "r"(a[2]), "r"(a[3]), "r"(b[0]), "r"(b[1]));
}

// ---------------------------------------------------------------------------
// dtype sniffer for input_ids (int32 vs int64)
// int64 little-endian: every odd 32-bit word is the (zero) high word.
// ---------------------------------------------------------------------------
__global__ void sniff_ids(const int* __restrict__ ids32) {
    if (threadIdx.x == 0 && blockIdx.x == 0) {
        int zeros = 0;
        for (int i = 1; i < 255; i += 2) zeros += (ids32[i] == 0);
        g_ids_is64 = (zeros > 64) ? 1 : 0;
    }
}

// ---------------------------------------------------------------------------
// tf32 mma.sync GEMM:  C[M,N] = (A@W + bias) * rowscale
//   A: MxK row-major (or gathered rows of emb table via ids when GATHER)
//   W: KxN row-major
//   rowscale(m) = 1 + strength*(gains[m]-1) when SCALE
// Block tile 128x128x32, 8 warps (4m x 2n), warp tile 32x64, m16n8k8 frags.
// Requires M%128==0, N%128==0, K%32==0 (true for all three calls).
// ---------------------------------------------------------------------------
#define BM 128
#define BN 128
#define BK 32

template<bool GATHER, bool SCALE>
__global__ __launch_bounds__(256, 2)
void gemm_tf32(const float* __restrict__ A, const void* __restrict__ idsv,
               const float* __restrict__ W, const float* __restrict__ bias,
               const float* __restrict__ gains, float strength,
               float* __restrict__ C, int M, int N, int K)
{
    __shared__ float As[BM][BK + 4];   // ld 36: conflict-free A frag loads
    __shared__ float Bs[BK][BN + 8];   // ld 136: conflict-free B frag loads

    const int tid = threadIdx.x;
    const int gm0 = blockIdx.x * BM;
    const int gn0 = blockIdx.y * BN;

    // per-thread A-row source pointers (4 rows, fixed across K loop)
    const float* arow[4];
    {
        const int r = tid >> 3;                      // 0..31
        const int is64 = GATHER ? g_ids_is64 : 0;
        #pragma unroll
        for (int i = 0; i < 4; i++) {
            const int grow = gm0 + r + i * 32;
            if (GATHER) {
                long long id = is64 ? ((const long long*)idsv)[grow]
                                    : (long long)((const int*)idsv)[grow];
                arow[i] = A + (size_t)id * K;
            } else {
                arow[i] = A + (size_t)grow * K;
            }
        }
    }
    const int ak4 = (tid & 7) * 4;
    const int bk  = tid >> 5;            // 0..7
    const int bn4 = (tid & 31) * 4;

    const int lane = tid & 31;
    const int wid  = tid >> 5;
    const int wm   = (wid & 3) * 32;
    const int wn   = (wid >> 2) * 64;
    const int ar   = lane >> 2;
    const int ac   = lane & 3;

    float acc[2][8][4];
    #pragma unroll
    for (int mi = 0; mi < 2; mi++)
        #pragma unroll
        for (int ni = 0; ni < 8; ni++)
            #pragma unroll
            for (int j = 0; j < 4; j++) acc[mi][ni][j] = 0.f;

    for (int k0 = 0; k0 < K; k0 += BK) {
        // ---- A tile (gmem -> smem, tf32 round) ----
        #pragma unroll
        for (int i = 0; i < 4; i++) {
            float4 v = *(const float4*)(arow[i] + k0 + ak4);
            v.x = tf32r(v.x); v.y = tf32r(v.y); v.z = tf32r(v.z); v.w = tf32r(v.w);
            *(float4*)&As[(tid >> 3) + i * 32][ak4] = v;
        }
        // ---- B tile ----
        #pragma unroll
        for (int i = 0; i < 4; i++) {
            float4 v = *(const float4*)(W + (size_t)(k0 + bk + i * 8) * N + gn0 + bn4);
            v.x = tf32r(v.x); v.y = tf32r(v.y); v.z = tf32r(v.z); v.w = tf32r(v.w);
            *(float4*)&Bs[bk + i * 8][bn4] = v;
        }
        __syncthreads();

        #pragma unroll
        for (int ks = 0; ks < BK; ks += 8) {
            unsigned a[2][4], b[8][2];
            #pragma unroll
            for (int mi = 0; mi < 2; mi++) {
                a[mi][0] = __float_as_uint(As[wm + mi*16 + ar    ][ks + ac    ]);
                a[mi][1] = __float_as_uint(As[wm + mi*16 + ar + 8][ks + ac    ]);
                a[mi][2] = __float_as_uint(As[wm + mi*16 + ar    ][ks + ac + 4]);
                a[mi][3] = __float_as_uint(As[wm + mi*16 + ar + 8][ks + ac + 4]);
            }
            #pragma unroll
            for (int ni = 0; ni < 8; ni++) {
                b[ni][0] = __float_as_uint(Bs[ks + ac    ][wn + ni*8 + ar]);
                b[ni][1] = __float_as_uint(Bs[ks + ac + 4][wn + ni*8 + ar]);
            }
            #pragma unroll
            for (int mi = 0; mi < 2; mi++)
                #pragma unroll
                for (int ni = 0; ni < 8; ni++)
                    mma8(acc[mi][ni], a[mi], b[ni]);
        }
        __syncthreads();
    }

    // ---- epilogue: bias + optional row scale ----
    #pragma unroll
    for (int mi = 0; mi < 2; mi++) {
        const int r0 = gm0 + wm + mi * 16 + ar;
        const int r1 = r0 + 8;
        float s0 = 1.f, s1 = 1.f;
        if (SCALE) {
            s0 = 1.f + strength * (gains[r0] - 1.f);
            s1 = 1.f + strength * (gains[r1] - 1.f);
        }
        #pragma unroll
        for (int ni = 0; ni < 8; ni++) {
            const int col = gn0 + wn + ni * 8 + ac * 2;
            const float b0 = bias[col], b1 = bias[col + 1];
            float2 o0, o1;
            o0.x = (acc[mi][ni][0] + b0) * s0;
            o0.y = (acc[mi][ni][1] + b1) * s0;
            o1.x = (acc[mi][ni][2] + b0) * s1;
            o1.y = (acc[mi][ni][3] + b1) * s1;
            *(float2*)&C[(size_t)r0 * N + col] = o0;
            *(float2*)&C[(size_t)r1 * N + col] = o1;
        }
    }
}

// ---------------------------------------------------------------------------
// GIF scan: per (b,d) channel, sequential over S (in place: cur -> spikes)
//   v' = 0.9 v + c ; s = sigmoid(4(v'-1)) ; v = v' - s
// sigmoid via ex2+rcp (MUFU, ~1 ulp) to keep full accuracy.
// ---------------------------------------------------------------------------
__global__ void gif_scan(float* __restrict__ buf, int D)
{
    const int t = blockIdx.x * blockDim.x + threadIdx.x;
    if (t >= B_ * D) return;
    const int b = t / D, d = t % D;
    float* p = buf + (size_t)b * S_ * D + d;

    const float KX = 4.0f * 1.4426950408889634f;  // 4*log2(e)
    float v = 0.f;
    #pragma unroll 1
    for (int s0 = 0; s0 < S_; s0 += 8) {
        float c[8];
        #pragma unroll
        for (int i = 0; i < 8; i++) c[i] = p[(size_t)(s0 + i) * D];
        #pragma unroll
        for (int i = 0; i < 8; i++) {
            v = fmaf(DECAY, v, c[i]);
            // exp(-4(v-1)) = 2^(KX*(1-v))
            const float e  = fast_ex2(fmaf(-KX, v, KX));
            const float sp = fast_rcp(1.0f + e);
            p[(size_t)(s0 + i) * D] = sp;
            v -= sp;
        }
    }
}

// ---------------------------------------------------------------------------
// launch
// ---------------------------------------------------------------------------
extern "C" void kernel_launch(void* const* d_in, const int* in_sizes, int n_in,
                              void* d_out, int out_size)
{
    const void*  ids   = d_in[0];                    // int32 or int64 (sniffed)
    const float* gains = (const float*)d_in[1];      // (B,S)
    const float* emb   = (const float*)d_in[2];      // (V,E)
    const float* encW  = (const float*)d_in[3];      // (E,H)
    const float* encb  = (const float*)d_in[4];      // (H)
    const float* decW  = (const float*)d_in[5];      // (H,E)
    const float* decb  = (const float*)d_in[6];      // (E)
    const float* outW  = (const float*)d_in[7];      // (E,V)
    const float* outb  = (const float*)d_in[8];      // (V)
    float* out = (float*)d_out;

    float *buf1, *buf2;
    cudaGetSymbolAddress((void**)&buf1, g_buf1);
    cudaGetSymbolAddress((void**)&buf2, g_buf2);

    sniff_ids<<<1, 32>>>((const int*)ids);

    // enc: cur1 = (gather(emb,ids) @ encW + encb) * (1+0.3*(g-1))   [4096 x 2048]
    gemm_tf32<true, true><<<dim3(M_/BM, H_/BN), 256>>>(
        emb, ids, encW, encb, gains, 0.3f, buf1, M_, H_, E_);
    gif_scan<<<(B_*H_ + 127) / 128, 128>>>(buf1, H_);

    // dec: cur2 = (spikes1 @ decW + decb) * (1+0.2*(g-1))           [4096 x 1024]
    gemm_tf32<false, true><<<dim3(M_/BM, E_/BN), 256>>>(
        buf1, nullptr, decW, decb, gains, 0.2f, buf2, M_, E_, H_);
    gif_scan<<<(B_*E_ + 127) / 128, 128>>>(buf2, E_);

    // out: logits = spikes2 @ outW + outb                           [4096 x 32000]
    gemm_tf32<false, false><<<dim3(M_/BM, V_/BN), 256>>>(
        buf2, nullptr, outW, outb, nullptr, 0.f, out, M_, V_, E_);
}